// round 5
// baseline (speedup 1.0000x reference)
#include <cuda_runtime.h>
#include <cuda_fp16.h>
#include <cstdint>

#define MM 256
#define OO 8192
#define II 8192
#define NNZ_TOTAL 3350528
#define NBUCKET 256          // 32-wide k buckets
#define NCH 128              // II/64 k-chunks
#define SMEM_BYTES 65536

__device__ __half         g_xh[MM * II];
__device__ unsigned short g_rk[NNZ_TOTAL];
__device__ __half         g_rv[NNZ_TOTAL];
__device__ int            g_roff[OO * (NBUCKET + 1)];
__device__ int            g_mode;   // 0=f16, 1=bf16, 2=f32

__device__ __forceinline__ uint32_t smem_u32(const void* p) {
    uint32_t a;
    asm("{ .reg .u64 t; cvta.to.shared.u64 t, %1; cvt.u32.u64 %0, t; }" : "=r"(a) : "l"(p));
    return a;
}
__device__ __forceinline__ uint32_t sw(uint32_t off) { return off ^ ((off >> 3) & 0x70u); }
// packed int32 holds ONE byte: low nibble -> even k, high nibble -> odd k; (value-8) exact in f16
__device__ __forceinline__ uint32_t dq(uint32_t v) {
    uint32_t h = 0x64006400u | (v & 0xFu) | ((v << 12) & 0x000F0000u);
    __half2 a = *reinterpret_cast<__half2*>(&h);
    uint32_t c8 = 0x64086408u;
    __half2 b = *reinterpret_cast<__half2*>(&c8);
    __half2 r = __hsub2(a, b);
    return *reinterpret_cast<uint32_t*>(&r);
}

// ---- dtype sniff for ortho_vals (harness may promote f16 -> f32 or bf16) ----
__global__ void sniff_vals(const unsigned short* __restrict__ p) {
    if (threadIdx.x != 0 || blockIdx.x != 0) return;
    bool ok16 = true, okbf = true;
    for (int j = 0; j < 128; j++) {
        unsigned short u = p[j];
        float h = __half2float(__ushort_as_half(u));
        ok16 = ok16 && (fabsf(h) < 0.5f);          // NaN -> false
        uint32_t bb = ((uint32_t)u) << 16;
        float b = __uint_as_float(bb);
        okbf = okbf && (fabsf(b) < 0.5f);
    }
    g_mode = ok16 ? 0 : (okbf ? 1 : 2);
}

__global__ void convert_x(const float* __restrict__ x) {
    int i = blockIdx.x * blockDim.x + threadIdx.x;
    if (i < MM * II / 4) {
        float4 v = reinterpret_cast<const float4*>(x)[i];
        reinterpret_cast<__half2*>(g_xh)[i * 2 + 0] = __floats2half2_rn(v.x, v.y);
        reinterpret_cast<__half2*>(g_xh)[i * 2 + 1] = __floats2half2_rn(v.z, v.w);
    }
}

// per-row counting sort of CSR entries into 32-wide k buckets; values pre-scaled by alpha/scale[o]
__global__ void residual_prep(const void* __restrict__ vals, const int* __restrict__ idx,
                              const int* __restrict__ ptr, const float* __restrict__ scales,
                              const float* __restrict__ alphap) {
    __shared__ int cnt[NBUCKET], run[NBUCKET], pref[NBUCKET + 1];
    const int o = blockIdx.x, t = threadIdx.x;
    const int s = ptr[o], e = ptr[o + 1], n = e - s;
    const int mode = g_mode;
    cnt[t] = 0; run[t] = 0;
    __syncthreads();
    for (int j = t; j < n; j += 256) atomicAdd(&cnt[idx[s + j] >> 5], 1);
    __syncthreads();
    if (t == 0) { int a = 0; for (int c = 0; c < NBUCKET; c++) { pref[c] = a; a += cnt[c]; } pref[NBUCKET] = a; }
    __syncthreads();
    g_roff[o * (NBUCKET + 1) + t] = s + pref[t];
    if (t == 0) g_roff[o * (NBUCKET + 1) + NBUCKET] = s + pref[NBUCKET];
    const float inv = alphap[0] / scales[o];
    for (int j = t; j < n; j += 256) {
        const int k = idx[s + j];
        const int pos = s + pref[k >> 5] + atomicAdd(&run[k >> 5], 1);
        float v;
        if (mode == 0)      v = __half2float(reinterpret_cast<const __half*>(vals)[s + j]);
        else if (mode == 1) v = __uint_as_float(((uint32_t)reinterpret_cast<const unsigned short*>(vals)[s + j]) << 16);
        else                v = reinterpret_cast<const float*>(vals)[s + j];
        g_rk[pos] = (unsigned short)k;
        g_rv[pos] = __float2half_rn(v * inv);
    }
}

// ---- fused dequant GEMM: out[256,8192] = x @ W^T, W = (q-8+res/scale)*scale ----
__device__ __forceinline__ void cpa_A(uint32_t Ab, int m_base, int k0, int tid) {
#pragma unroll
    for (int r = 0; r < 4; r++) {
        const int u = tid + r * 256, row = u >> 3, seg = u & 7;
        const __half* src = g_xh + (size_t)(m_base + row) * II + k0 + seg * 8;
        uint32_t ad = Ab + sw((uint32_t)(row * 128 + seg * 16));
        asm volatile("cp.async.cg.shared.global [%0], [%1], 16;" :: "r"(ad), "l"(src));
    }
    asm volatile("cp.async.commit_group;" ::: "memory");
}
__device__ __forceinline__ void ldg_B(const int* __restrict__ packed, int o_base, int k0, int tid, uint4* pk) {
    const uint4* src = reinterpret_cast<const uint4*>(
        packed + (size_t)(o_base + (tid >> 1)) * (II / 2) + (k0 >> 1) + (tid & 1) * 16);
#pragma unroll
    for (int j = 0; j < 4; j++) pk[j] = src[j];
}
__device__ __forceinline__ void sts_B(uint32_t Bb, const uint4* pk, int tid) {
    const int row = tid >> 1, h = tid & 1;
#pragma unroll
    for (int j = 0; j < 4; j++) {
        uint32_t ad = Bb + sw((uint32_t)(row * 128 + (h * 4 + j) * 16));
        asm volatile("st.shared.v4.b32 [%0], {%1,%2,%3,%4};"
                     :: "r"(ad), "r"(dq(pk[j].x)), "r"(dq(pk[j].y)), "r"(dq(pk[j].z)), "r"(dq(pk[j].w)) : "memory");
    }
}
__device__ __forceinline__ void fold_res(uint32_t Bb, int o_base, int k0, int tid) {
    const int row = tid >> 1, h = tid & 1;
    const int o = o_base + row;
    const int b = (k0 >> 5) + h;
    const int s0 = g_roff[o * (NBUCKET + 1) + b];
    const int s1 = g_roff[o * (NBUCKET + 1) + b + 1];
    const int kb = k0 + h * 32;
    for (int j = s0; j < s1; j++) {
        const int kl = (int)g_rk[j] - kb;
        uint32_t ad = Bb + sw((uint32_t)(row * 128 + h * 64 + kl * 2));
        unsigned short u;
        asm volatile("ld.shared.b16 %0, [%1];" : "=h"(u) : "r"(ad));
        __half v = __hadd(__ushort_as_half(u), g_rv[j]);
        u = __half_as_ushort(v);
        asm volatile("st.shared.b16 [%0], %1;" :: "r"(ad), "h"(u) : "memory");
    }
}

__global__ void __launch_bounds__(256, 1)
gemm_kernel(const int* __restrict__ packed, const float* __restrict__ scales, float* __restrict__ out) {
    extern __shared__ char smem[];
    const uint32_t sb = smem_u32(smem);
    const int tid = threadIdx.x, wid = tid >> 5, lane = tid & 31;
    const int wm = wid >> 2, wn = wid & 3;                 // warp tile 64x32
    const int n_idx = blockIdx.x >> 1, m_idx = blockIdx.x & 1;
    const int o_base = n_idx * 128, m_base = m_idx * 128;
    const uint32_t A[2] = { sb, sb + 32768u };
    const uint32_t B[2] = { sb + 16384u, sb + 49152u };

    float c[4][4][4];
#pragma unroll
    for (int mt = 0; mt < 4; mt++)
#pragma unroll
        for (int nt = 0; nt < 4; nt++)
#pragma unroll
            for (int q = 0; q < 4; q++) c[mt][nt][q] = 0.f;

    {
        uint4 pk[4];
        cpa_A(A[0], m_base, 0, tid);
        ldg_B(packed, o_base, 0, tid, pk);
        sts_B(B[0], pk, tid);
        fold_res(B[0], o_base, 0, tid);
        asm volatile("cp.async.wait_group 0;" ::: "memory");
        __syncthreads();
    }

    for (int ch = 0; ch < NCH; ch++) {
        const int cur = ch & 1, nxt = cur ^ 1;
        uint4 pk[4];
        if (ch + 1 < NCH) {
            cpa_A(A[nxt], m_base, (ch + 1) * 64, tid);
            ldg_B(packed, o_base, (ch + 1) * 64, tid, pk);
        }
#pragma unroll
        for (int kk = 0; kk < 4; kk++) {
            uint32_t a[4][4], b[4][2];
#pragma unroll
            for (int mt = 0; mt < 4; mt++) {
                const int row = wm * 64 + mt * 16 + (lane & 15);
                uint32_t ad = A[cur] + sw((uint32_t)(row * 128 + kk * 32 + (lane >> 4) * 16));
                asm volatile("ldmatrix.sync.aligned.m8n8.x4.shared.b16 {%0,%1,%2,%3}, [%4];"
                             : "=r"(a[mt][0]), "=r"(a[mt][1]), "=r"(a[mt][2]), "=r"(a[mt][3]) : "r"(ad));
            }
#pragma unroll
            for (int nt = 0; nt < 4; nt++) {
                const int row = wn * 32 + nt * 8 + (lane & 7);
                uint32_t ad = B[cur] + sw((uint32_t)(row * 128 + kk * 32 + ((lane >> 3) & 1) * 16));
                asm volatile("ldmatrix.sync.aligned.m8n8.x2.shared.b16 {%0,%1}, [%2];"
                             : "=r"(b[nt][0]), "=r"(b[nt][1]) : "r"(ad));
            }
#pragma unroll
            for (int mt = 0; mt < 4; mt++)
#pragma unroll
                for (int nt = 0; nt < 4; nt++)
                    asm volatile("mma.sync.aligned.m16n8k16.row.col.f32.f16.f16.f32 "
                                 "{%0,%1,%2,%3}, {%4,%5,%6,%7}, {%8,%9}, {%0,%1,%2,%3};"
                                 : "+f"(c[mt][nt][0]), "+f"(c[mt][nt][1]), "+f"(c[mt][nt][2]), "+f"(c[mt][nt][3])
                                 : "r"(a[mt][0]), "r"(a[mt][1]), "r"(a[mt][2]), "r"(a[mt][3]),
                                   "r"(b[nt][0]), "r"(b[nt][1]));
        }
        if (ch + 1 < NCH) {
            sts_B(B[nxt], pk, tid);
            fold_res(B[nxt], o_base, (ch + 1) * 64, tid);
            asm volatile("cp.async.wait_group 0;" ::: "memory");
        }
        __syncthreads();
    }

#pragma unroll
    for (int mt = 0; mt < 4; mt++) {
        const int m0 = m_base + wm * 64 + mt * 16 + (lane >> 2);
#pragma unroll
        for (int nt = 0; nt < 4; nt++) {
            const int o = o_base + wn * 32 + nt * 8 + (lane & 3) * 2;
            const float2 s = *reinterpret_cast<const float2*>(scales + o);
            float2 r0, r1;
            r0.x = c[mt][nt][0] * s.x; r0.y = c[mt][nt][1] * s.y;
            r1.x = c[mt][nt][2] * s.x; r1.y = c[mt][nt][3] * s.y;
            *reinterpret_cast<float2*>(out + (size_t)m0 * OO + o) = r0;
            *reinterpret_cast<float2*>(out + (size_t)(m0 + 8) * OO + o) = r1;
        }
    }
}

extern "C" void kernel_launch(void* const* d_in, const int* in_sizes, int n_in,
                              void* d_out, int out_size) {
    const float* x      = (const float*)d_in[0];
    const int*   packed = (const int*)d_in[1];
    const float* scales = (const float*)d_in[2];
    const void*  vals   = (const void*)d_in[3];
    const int*   idx    = (const int*)d_in[4];
    const int*   ptr    = (const int*)d_in[5];
    const float* alpha  = (const float*)d_in[6];
    float* out = (float*)d_out;

    cudaFuncSetAttribute(gemm_kernel, cudaFuncAttributeMaxDynamicSharedMemorySize, SMEM_BYTES);
    sniff_vals<<<1, 32>>>((const unsigned short*)vals);
    convert_x<<<2048, 256>>>(x);
    residual_prep<<<OO, 256>>>(vals, idx, ptr, scales, alpha);
    gemm_kernel<<<128, 256, SMEM_BYTES>>>(packed, scales, out);
}

// round 7
// speedup vs baseline: 1.1296x; 1.1296x over previous
#include <cuda_runtime.h>
#include <cuda_fp16.h>
#include <cstdint>

#define MM 256
#define OO 8192
#define II 8192
#define NNZ_TOTAL 3350528
#define NBUCKET 256          // 32-wide k buckets
#define NCH 128              // II/64 k-chunks
#define SMEM_BYTES 65536

__device__ __half         g_xh[MM * II];
__device__ unsigned short g_rk[NNZ_TOTAL];
__device__ __half         g_rv[NNZ_TOTAL];
__device__ int            g_roff[OO * (NBUCKET + 1)];
__device__ int            g_mode;   // 0=f16, 1=bf16, 2=f32

__device__ __forceinline__ uint32_t smem_u32(const void* p) {
    uint32_t a;
    asm("{ .reg .u64 t; cvta.to.shared.u64 t, %1; cvt.u32.u64 %0, t; }" : "=r"(a) : "l"(p));
    return a;
}
__device__ __forceinline__ uint32_t sw(uint32_t off) { return off ^ ((off >> 3) & 0x70u); }
__device__ __forceinline__ uint32_t dq(uint32_t v) {
    uint32_t h = 0x64006400u | (v & 0xFu) | ((v << 12) & 0x000F0000u);
    __half2 a = *reinterpret_cast<__half2*>(&h);
    uint32_t c8 = 0x64086408u;
    __half2 b = *reinterpret_cast<__half2*>(&c8);
    __half2 r = __hsub2(a, b);
    return *reinterpret_cast<uint32_t*>(&r);
}

__global__ void sniff_vals(const unsigned short* __restrict__ p) {
    if (threadIdx.x != 0 || blockIdx.x != 0) return;
    bool ok16 = true, okbf = true;
    for (int j = 0; j < 128; j++) {
        unsigned short u = p[j];
        float h = __half2float(__ushort_as_half(u));
        ok16 = ok16 && (fabsf(h) < 0.5f);
        uint32_t bb = ((uint32_t)u) << 16;
        float b = __uint_as_float(bb);
        okbf = okbf && (fabsf(b) < 0.5f);
    }
    g_mode = ok16 ? 0 : (okbf ? 1 : 2);
}

__global__ void convert_x(const float* __restrict__ x) {
    int i = blockIdx.x * blockDim.x + threadIdx.x;
    if (i < MM * II / 4) {
        float4 v = reinterpret_cast<const float4*>(x)[i];
        reinterpret_cast<__half2*>(g_xh)[i * 2 + 0] = __floats2half2_rn(v.x, v.y);
        reinterpret_cast<__half2*>(g_xh)[i * 2 + 1] = __floats2half2_rn(v.z, v.w);
    }
}

__global__ void residual_prep(const void* __restrict__ vals, const int* __restrict__ idx,
                              const int* __restrict__ ptr, const float* __restrict__ scales,
                              const float* __restrict__ alphap) {
    __shared__ int cnt[NBUCKET], run[NBUCKET], pref[NBUCKET + 1];
    const int o = blockIdx.x, t = threadIdx.x;
    const int s = ptr[o], e = ptr[o + 1], n = e - s;
    const int mode = g_mode;
    cnt[t] = 0; run[t] = 0;
    __syncthreads();
    for (int j = t; j < n; j += 256) atomicAdd(&cnt[idx[s + j] >> 5], 1);
    __syncthreads();
    if (t == 0) { int a = 0; for (int c = 0; c < NBUCKET; c++) { pref[c] = a; a += cnt[c]; } pref[NBUCKET] = a; }
    __syncthreads();
    g_roff[o * (NBUCKET + 1) + t] = s + pref[t];
    if (t == 0) g_roff[o * (NBUCKET + 1) + NBUCKET] = s + pref[NBUCKET];
    const float inv = alphap[0] / scales[o];
    for (int j = t; j < n; j += 256) {
        const int k = idx[s + j];
        const int pos = s + pref[k >> 5] + atomicAdd(&run[k >> 5], 1);
        float v;
        if (mode == 0)      v = __half2float(reinterpret_cast<const __half*>(vals)[s + j]);
        else if (mode == 1) v = __uint_as_float(((uint32_t)reinterpret_cast<const unsigned short*>(vals)[s + j]) << 16);
        else                v = reinterpret_cast<const float*>(vals)[s + j];
        g_rk[pos] = (unsigned short)k;
        g_rv[pos] = __float2half_rn(v * inv);
    }
}

// ---- fused dequant GEMM: out[256,8192] = x @ W^T ----
__device__ __forceinline__ void cpa_A(uint32_t Ab, int m_base, int k0, int tid) {
#pragma unroll
    for (int r = 0; r < 2; r++) {
        const int u = tid + r * 512, row = u >> 3, seg = u & 7;
        const __half* src = g_xh + (size_t)(m_base + row) * II + k0 + seg * 8;
        uint32_t ad = Ab + sw((uint32_t)(row * 128 + seg * 16));
        asm volatile("cp.async.cg.shared.global [%0], [%1], 16;" :: "r"(ad), "l"(src));
    }
    asm volatile("cp.async.commit_group;" ::: "memory");
}
__device__ __forceinline__ void ldg_B(const int* __restrict__ packed, int o_base, int k0, int tid, uint4* pk) {
#pragma unroll
    for (int r = 0; r < 2; r++) {
        const int u = tid + r * 512, row = u >> 3, seg = u & 7;
        pk[r] = *reinterpret_cast<const uint4*>(
            packed + (size_t)(o_base + row) * (II / 2) + (k0 >> 1) + seg * 4);
    }
}
__device__ __forceinline__ void sts_B(uint32_t Bb, const uint4* pk, int tid) {
#pragma unroll
    for (int r = 0; r < 2; r++) {
        const int u = tid + r * 512, row = u >> 3, seg = u & 7;
        uint32_t ad = Bb + sw((uint32_t)(row * 128 + seg * 16));
        asm volatile("st.shared.v4.b32 [%0], {%1,%2,%3,%4};"
                     :: "r"(ad), "r"(dq(pk[r].x)), "r"(dq(pk[r].y)), "r"(dq(pk[r].z)), "r"(dq(pk[r].w)) : "memory");
    }
}
__device__ __forceinline__ void fold_res(uint32_t Bb, int o_base, int k0, int tid) {
    if (tid >= 256) return;
    const int row = tid >> 1, h = tid & 1;
    const int o = o_base + row;
    const int b = (k0 >> 5) + h;
    const int s0 = g_roff[o * (NBUCKET + 1) + b];
    const int s1 = g_roff[o * (NBUCKET + 1) + b + 1];
    const int kb = k0 + h * 32;
    for (int j = s0; j < s1; j++) {
        const int kl = (int)g_rk[j] - kb;
        uint32_t ad = Bb + sw((uint32_t)(row * 128 + h * 64 + kl * 2));
        unsigned short u;
        asm volatile("ld.shared.b16 %0, [%1];" : "=h"(u) : "r"(ad));
        __half v = __hadd(__ushort_as_half(u), g_rv[j]);
        u = __half_as_ushort(v);
        asm volatile("st.shared.b16 [%0], %1;" :: "r"(ad), "h"(u) : "memory");
    }
}

__global__ void __launch_bounds__(512, 1)
gemm_kernel(const int* __restrict__ packed, const float* __restrict__ scales, float* __restrict__ out) {
    extern __shared__ char smem[];
    const uint32_t sb = smem_u32(smem);
    const int tid = threadIdx.x, wid = tid >> 5, lane = tid & 31;
    const int wm = wid >> 2, wn = wid & 3;                 // 4x4 warps, warp tile 32x32
    const int n_idx = blockIdx.x >> 1, m_idx = blockIdx.x & 1;
    const int o_base = n_idx * 128, m_base = m_idx * 128;
    const uint32_t A[2] = { sb, sb + 32768u };
    const uint32_t B[2] = { sb + 16384u, sb + 49152u };

    float c[2][4][4];
#pragma unroll
    for (int mt = 0; mt < 2; mt++)
#pragma unroll
        for (int nt = 0; nt < 4; nt++)
#pragma unroll
            for (int q = 0; q < 4; q++) c[mt][nt][q] = 0.f;

    {
        uint4 pk[2];
        cpa_A(A[0], m_base, 0, tid);
        ldg_B(packed, o_base, 0, tid, pk);
        sts_B(B[0], pk, tid);
        __syncthreads();               // STS visible before cross-thread fold RMW
        fold_res(B[0], o_base, 0, tid);
        asm volatile("cp.async.wait_group 0;" ::: "memory");
        __syncthreads();
    }

    for (int ch = 0; ch < NCH; ch++) {
        const int cur = ch & 1, nxt = cur ^ 1;
        uint4 pk[2];
        if (ch + 1 < NCH) {
            cpa_A(A[nxt], m_base, (ch + 1) * 64, tid);
            ldg_B(packed, o_base, (ch + 1) * 64, tid, pk);
        }
#pragma unroll
        for (int kk = 0; kk < 4; kk++) {
            uint32_t a[2][4], b[4][2];
#pragma unroll
            for (int mt = 0; mt < 2; mt++) {
                const int row = wm * 32 + mt * 16 + (lane & 15);
                uint32_t ad = A[cur] + sw((uint32_t)(row * 128 + kk * 32 + (lane >> 4) * 16));
                asm volatile("ldmatrix.sync.aligned.m8n8.x4.shared.b16 {%0,%1,%2,%3}, [%4];"
                             : "=r"(a[mt][0]), "=r"(a[mt][1]), "=r"(a[mt][2]), "=r"(a[mt][3]) : "r"(ad));
            }
#pragma unroll
            for (int ntp = 0; ntp < 2; ntp++) {
                const int row = wn * 32 + ntp * 16 + ((lane >> 4) & 1) * 8 + (lane & 7);
                uint32_t ad = B[cur] + sw((uint32_t)(row * 128 + kk * 32 + ((lane >> 3) & 1) * 16));
                asm volatile("ldmatrix.sync.aligned.m8n8.x4.shared.b16 {%0,%1,%2,%3}, [%4];"
                             : "=r"(b[2 * ntp][0]), "=r"(b[2 * ntp][1]),
                               "=r"(b[2 * ntp + 1][0]), "=r"(b[2 * ntp + 1][1]) : "r"(ad));
            }
#pragma unroll
            for (int mt = 0; mt < 2; mt++)
#pragma unroll
                for (int nt = 0; nt < 4; nt++)
                    asm volatile("mma.sync.aligned.m16n8k16.row.col.f32.f16.f16.f32 "
                                 "{%0,%1,%2,%3}, {%4,%5,%6,%7}, {%8,%9}, {%0,%1,%2,%3};"
                                 : "+f"(c[mt][nt][0]), "+f"(c[mt][nt][1]), "+f"(c[mt][nt][2]), "+f"(c[mt][nt][3])
                                 : "r"(a[mt][0]), "r"(a[mt][1]), "r"(a[mt][2]), "r"(a[mt][3]),
                                   "r"(b[nt][0]), "r"(b[nt][1]));
        }
        if (ch + 1 < NCH) {
            sts_B(B[nxt], pk, tid);
            __syncthreads();           // STS visible before cross-thread fold RMW
            fold_res(B[nxt], o_base, (ch + 1) * 64, tid);
            asm volatile("cp.async.wait_group 0;" ::: "memory");
        }
        __syncthreads();
    }

#pragma unroll
    for (int mt = 0; mt < 2; mt++) {
        const int m0 = m_base + wm * 32 + mt * 16 + (lane >> 2);
#pragma unroll
        for (int nt = 0; nt < 4; nt++) {
            const int o = o_base + wn * 32 + nt * 8 + (lane & 3) * 2;
            const float2 s = *reinterpret_cast<const float2*>(scales + o);
            float2 r0, r1;
            r0.x = c[mt][nt][0] * s.x; r0.y = c[mt][nt][1] * s.y;
            r1.x = c[mt][nt][2] * s.x; r1.y = c[mt][nt][3] * s.y;
            *reinterpret_cast<float2*>(out + (size_t)m0 * OO + o) = r0;
            *reinterpret_cast<float2*>(out + (size_t)(m0 + 8) * OO + o) = r1;
        }
    }
}

extern "C" void kernel_launch(void* const* d_in, const int* in_sizes, int n_in,
                              void* d_out, int out_size) {
    const float* x      = (const float*)d_in[0];
    const int*   packed = (const int*)d_in[1];
    const float* scales = (const float*)d_in[2];
    const void*  vals   = (const void*)d_in[3];
    const int*   idx    = (const int*)d_in[4];
    const int*   ptr    = (const int*)d_in[5];
    const float* alpha  = (const float*)d_in[6];
    float* out = (float*)d_out;

    cudaFuncSetAttribute(gemm_kernel, cudaFuncAttributeMaxDynamicSharedMemorySize, SMEM_BYTES);
    sniff_vals<<<1, 32>>>((const unsigned short*)vals);
    convert_x<<<2048, 256>>>(x);
    residual_prep<<<OO, 256>>>(vals, idx, ptr, scales, alpha);
    gemm_kernel<<<128, 512, SMEM_BYTES>>>(packed, scales, out);
}

// round 8
// speedup vs baseline: 1.4700x; 1.3013x over previous
#include <cuda_runtime.h>
#include <cuda_fp16.h>
#include <cstdint>

#define MM 256
#define OO 8192
#define II 8192
#define NNZ_TOTAL 3350528
#define NBUCKET 256          // 32-wide k buckets
#define NITER 64             // II / 128
#define STAGES 3
#define STAGE_BYTES 65536    // A 32KB + B 32KB
#define SMEM_BYTES (STAGES * STAGE_BYTES)   // 196608

__device__ __half         g_xh[MM * II];
__device__ unsigned short g_rk[NNZ_TOTAL];
__device__ __half         g_rv[NNZ_TOTAL];
__device__ int            g_roff[OO * (NBUCKET + 1)];
__device__ int            g_mode;   // 0=f16, 1=bf16, 2=f32

__device__ __forceinline__ uint32_t smem_u32(const void* p) {
    uint32_t a;
    asm("{ .reg .u64 t; cvta.to.shared.u64 t, %1; cvt.u32.u64 %0, t; }" : "=r"(a) : "l"(p));
    return a;
}
__device__ __forceinline__ uint32_t sw(uint32_t off) { return off ^ ((off >> 3) & 0x70u); }
// one packed int32 holds ONE byte: low nibble -> even k, high nibble -> odd k; (value-8) exact in f16
__device__ __forceinline__ uint32_t dq(uint32_t v) {
    uint32_t h = 0x64006400u | (v & 0xFu) | ((v << 12) & 0x000F0000u);
    __half2 a = *reinterpret_cast<__half2*>(&h);
    uint32_t c8 = 0x64086408u;
    __half2 b = *reinterpret_cast<__half2*>(&c8);
    __half2 r = __hsub2(a, b);
    return *reinterpret_cast<uint32_t*>(&r);
}

__global__ void sniff_vals(const unsigned short* __restrict__ p) {
    if (threadIdx.x != 0 || blockIdx.x != 0) return;
    bool ok16 = true, okbf = true;
    for (int j = 0; j < 128; j++) {
        unsigned short u = p[j];
        float h = __half2float(__ushort_as_half(u));
        ok16 = ok16 && (fabsf(h) < 0.5f);
        uint32_t bb = ((uint32_t)u) << 16;
        float b = __uint_as_float(bb);
        okbf = okbf && (fabsf(b) < 0.5f);
    }
    g_mode = ok16 ? 0 : (okbf ? 1 : 2);
}

__global__ void convert_x(const float* __restrict__ x) {
    int i = blockIdx.x * blockDim.x + threadIdx.x;
    if (i < MM * II / 4) {
        float4 v = reinterpret_cast<const float4*>(x)[i];
        reinterpret_cast<__half2*>(g_xh)[i * 2 + 0] = __floats2half2_rn(v.x, v.y);
        reinterpret_cast<__half2*>(g_xh)[i * 2 + 1] = __floats2half2_rn(v.z, v.w);
    }
}

__global__ void residual_prep(const void* __restrict__ vals, const int* __restrict__ idx,
                              const int* __restrict__ ptr, const float* __restrict__ scales,
                              const float* __restrict__ alphap) {
    __shared__ int cnt[NBUCKET], run[NBUCKET], pref[NBUCKET + 1];
    const int o = blockIdx.x, t = threadIdx.x;
    const int s = ptr[o], e = ptr[o + 1], n = e - s;
    const int mode = g_mode;
    cnt[t] = 0; run[t] = 0;
    __syncthreads();
    for (int j = t; j < n; j += 256) atomicAdd(&cnt[idx[s + j] >> 5], 1);
    __syncthreads();
    if (t == 0) { int a = 0; for (int c = 0; c < NBUCKET; c++) { pref[c] = a; a += cnt[c]; } pref[NBUCKET] = a; }
    __syncthreads();
    g_roff[o * (NBUCKET + 1) + t] = s + pref[t];
    if (t == 0) g_roff[o * (NBUCKET + 1) + NBUCKET] = s + pref[NBUCKET];
    const float inv = alphap[0] / scales[o];
    for (int j = t; j < n; j += 256) {
        const int k = idx[s + j];
        const int pos = s + pref[k >> 5] + atomicAdd(&run[k >> 5], 1);
        float v;
        if (mode == 0)      v = __half2float(reinterpret_cast<const __half*>(vals)[s + j]);
        else if (mode == 1) v = __uint_as_float(((uint32_t)reinterpret_cast<const unsigned short*>(vals)[s + j]) << 16);
        else                v = reinterpret_cast<const float*>(vals)[s + j];
        g_rk[pos] = (unsigned short)k;
        g_rv[pos] = __float2half_rn(v * inv);
    }
}

// ---- fused dequant GEMM: out[256,8192] = x @ W^T ----
// CTA tile 128(m) x 128(o), K chunks of 128, 3-stage pipeline, 512 threads.
// Stage layout: A = two 16KB SW128 halves (k 0..63 | 64..127), then B likewise.
__device__ __forceinline__ void cpa_A(uint32_t Ab, int m_base, int k0, int tid) {
#pragma unroll
    for (int r = 0; r < 4; r++) {
        const int u = tid + r * 512, row = u >> 4, seg = u & 15;
        const __half* src = g_xh + (size_t)(m_base + row) * II + k0 + seg * 8;
        uint32_t off = ((uint32_t)(seg >> 3) << 14) + (uint32_t)(row * 128 + (seg & 7) * 16);
        asm volatile("cp.async.cg.shared.global [%0], [%1], 16;" :: "r"(Ab + sw(off)), "l"(src));
    }
    asm volatile("cp.async.commit_group;" ::: "memory");
}
__device__ __forceinline__ void ldg_B(const int* __restrict__ packed, int o_base, int k0, int tid, uint4* pk) {
    const int row = tid >> 2, seg = tid & 3;
    const uint4* src = reinterpret_cast<const uint4*>(
        packed + (size_t)(o_base + row) * (II / 2) + (k0 >> 1) + seg * 16);
#pragma unroll
    for (int j = 0; j < 4; j++) pk[j] = src[j];
}
__device__ __forceinline__ void sts_fold_B(uint32_t Bb, const uint4* pk, int o_base, int k0, int tid) {
    const int row = tid >> 2, seg = tid & 3;
    const uint32_t hb = ((uint32_t)(seg >> 1) << 14) + (uint32_t)(row * 128 + (seg & 1) * 64);
#pragma unroll
    for (int j = 0; j < 4; j++) {
        uint32_t ad = Bb + sw(hb + j * 16);
        asm volatile("st.shared.v4.b32 [%0], {%1,%2,%3,%4};"
                     :: "r"(ad), "r"(dq(pk[j].x)), "r"(dq(pk[j].y)), "r"(dq(pk[j].z)), "r"(dq(pk[j].w)) : "memory");
    }
    // residual fold: same thread owns this (row, 32-k) window -> no barrier needed
    const int o = o_base + row;
    const int b = (k0 >> 5) + seg;
    const int s0 = g_roff[o * (NBUCKET + 1) + b];
    const int s1 = g_roff[o * (NBUCKET + 1) + b + 1];
    const int kb = k0 + seg * 32;
    for (int j = s0; j < s1; j++) {
        const int kl = (int)g_rk[j] - kb;
        uint32_t ad = Bb + sw(hb + (uint32_t)(kl * 2));
        unsigned short u;
        asm volatile("ld.shared.b16 %0, [%1];" : "=h"(u) : "r"(ad));
        __half v = __hadd(__ushort_as_half(u), g_rv[j]);
        u = __half_as_ushort(v);
        asm volatile("st.shared.b16 [%0], %1;" :: "r"(ad), "h"(u) : "memory");
    }
}

__global__ void __launch_bounds__(512, 1)
gemm_kernel(const int* __restrict__ packed, const float* __restrict__ scales, float* __restrict__ out) {
    extern __shared__ char smem[];
    const uint32_t sb = smem_u32(smem);
    const int tid = threadIdx.x, wid = tid >> 5, lane = tid & 31;
    const int wm = wid >> 2, wn = wid & 3;                 // 4x4 warps, warp tile 32x32
    const int n_idx = blockIdx.x >> 1, m_idx = blockIdx.x & 1;
    const int o_base = n_idx * 128, m_base = m_idx * 128;

    float c[2][4][4];
#pragma unroll
    for (int mt = 0; mt < 2; mt++)
#pragma unroll
        for (int nt = 0; nt < 4; nt++)
#pragma unroll
            for (int q = 0; q < 4; q++) c[mt][nt][q] = 0.f;

    // prologue: fill stages 0,1  (groups g0, g1)
#pragma unroll
    for (int s = 0; s < STAGES - 1; s++) {
        const uint32_t base = sb + s * STAGE_BYTES;
        cpa_A(base, m_base, s * 128, tid);
        uint4 pk[4];
        ldg_B(packed, o_base, s * 128, tid, pk);
        sts_fold_B(base + 32768u, pk, o_base, s * 128, tid);
    }

    for (int ch = 0; ch < NITER; ch++) {
        const uint32_t cur = sb + (uint32_t)(ch % STAGES) * STAGE_BYTES;
        // stage ch's A group must be done; 1 newer group (stage ch+1) may be pending
        if (ch == NITER - 1) asm volatile("cp.async.wait_group 0;" ::: "memory");
        else                 asm volatile("cp.async.wait_group 1;" ::: "memory");
        __syncthreads();   // stage ch visible; all warps done computing ch-1 -> safe to refill its buffer

        uint4 pk[4];
        const bool produce = (ch + STAGES - 1) < NITER;
        const int pch = ch + STAGES - 1;
        const uint32_t pbase = sb + (uint32_t)(pch % STAGES) * STAGE_BYTES;
        if (produce) {
            ldg_B(packed, o_base, pch * 128, tid, pk);     // long-latency LDGs issued early
            cpa_A(pbase, m_base, pch * 128, tid);          // commit group g(pch)
        }

#pragma unroll
        for (int kk = 0; kk < 8; kk++) {
            const uint32_t khoff = ((uint32_t)(kk >> 2) << 14);
            const int kkl = kk & 3;
            uint32_t a[2][4], b[4][2];
#pragma unroll
            for (int mt = 0; mt < 2; mt++) {
                const int row = wm * 32 + mt * 16 + (lane & 15);
                uint32_t ad = cur + sw(khoff + (uint32_t)(row * 128 + kkl * 32 + (lane >> 4) * 16));
                asm volatile("ldmatrix.sync.aligned.m8n8.x4.shared.b16 {%0,%1,%2,%3}, [%4];"
                             : "=r"(a[mt][0]), "=r"(a[mt][1]), "=r"(a[mt][2]), "=r"(a[mt][3]) : "r"(ad));
            }
#pragma unroll
            for (int ntp = 0; ntp < 2; ntp++) {
                const int row = wn * 32 + ntp * 16 + ((lane >> 4) & 1) * 8 + (lane & 7);
                uint32_t ad = cur + 32768u + sw(khoff + (uint32_t)(row * 128 + kkl * 32 + ((lane >> 3) & 1) * 16));
                asm volatile("ldmatrix.sync.aligned.m8n8.x4.shared.b16 {%0,%1,%2,%3}, [%4];"
                             : "=r"(b[2 * ntp][0]), "=r"(b[2 * ntp][1]),
                               "=r"(b[2 * ntp + 1][0]), "=r"(b[2 * ntp + 1][1]) : "r"(ad));
            }
#pragma unroll
            for (int mt = 0; mt < 2; mt++)
#pragma unroll
                for (int nt = 0; nt < 4; nt++)
                    asm volatile("mma.sync.aligned.m16n8k16.row.col.f32.f16.f16.f32 "
                                 "{%0,%1,%2,%3}, {%4,%5,%6,%7}, {%8,%9}, {%0,%1,%2,%3};"
                                 : "+f"(c[mt][nt][0]), "+f"(c[mt][nt][1]), "+f"(c[mt][nt][2]), "+f"(c[mt][nt][3])
                                 : "r"(a[mt][0]), "r"(a[mt][1]), "r"(a[mt][2]), "r"(a[mt][3]),
                                   "r"(b[nt][0]), "r"(b[nt][1]));
        }

        if (produce)
            sts_fold_B(pbase + 32768u, pk, o_base, pch * 128, tid);  // own stores only; visible via next iters' barriers
    }

    // epilogue: per-o scale in fp32, direct float2 stores
#pragma unroll
    for (int mt = 0; mt < 2; mt++) {
        const int m0 = m_base + wm * 32 + mt * 16 + (lane >> 2);
#pragma unroll
        for (int nt = 0; nt < 4; nt++) {
            const int o = o_base + wn * 32 + nt * 8 + (lane & 3) * 2;
            const float2 s = *reinterpret_cast<const float2*>(scales + o);
            float2 r0, r1;
            r0.x = c[mt][nt][0] * s.x; r0.y = c[mt][nt][1] * s.y;
            r1.x = c[mt][nt][2] * s.x; r1.y = c[mt][nt][3] * s.y;
            *reinterpret_cast<float2*>(out + (size_t)m0 * OO + o) = r0;
            *reinterpret_cast<float2*>(out + (size_t)(m0 + 8) * OO + o) = r1;
        }
    }
}

extern "C" void kernel_launch(void* const* d_in, const int* in_sizes, int n_in,
                              void* d_out, int out_size) {
    const float* x      = (const float*)d_in[0];
    const int*   packed = (const int*)d_in[1];
    const float* scales = (const float*)d_in[2];
    const void*  vals   = (const void*)d_in[3];
    const int*   idx    = (const int*)d_in[4];
    const int*   ptr    = (const int*)d_in[5];
    const float* alpha  = (const float*)d_in[6];
    float* out = (float*)d_out;

    cudaFuncSetAttribute(gemm_kernel, cudaFuncAttributeMaxDynamicSharedMemorySize, SMEM_BYTES);
    sniff_vals<<<1, 32>>>((const unsigned short*)vals);
    convert_x<<<2048, 256>>>(x);
    residual_prep<<<OO, 256>>>(vals, idx, ptr, scales, alpha);
    gemm_kernel<<<128, 512, SMEM_BYTES>>>(packed, scales, out);
}